// round 2
// baseline (speedup 1.0000x reference)
#include <cuda_runtime.h>

// SelfAttention: B=16, E=42, n=E*E=1764 tokens, D=256.
// out[b,n,:256] = x ; out[b,n,256:] = softmax(x*dot_scale @ m^T + mask_bias) @ m
// (input_dot = x @ w_lin^T is constant along the softmax axis -> cancels; w_lin unused)

#define NB      16
#define NE      42
#define NTOK    (NE*NE)     // 1764
#define DD      256
#define BM      64          // query rows per CTA
#define BN      64          // keys per inner tile
#define QP      68          // padded pitch for transposed smem tiles (gcd(68,32)=4 -> 8 banks)
#define NQT     28          // ceil(1764/64)
#define NKT     28
#define NTHREADS 256

__device__ int g_mask_is4;  // 1 if mask elements are 4 bytes wide, 0 if 1 byte

// ---------------------------------------------------------------------------
// packed fp32x2 helpers (Blackwell FFMA2: 2x fp32 FMA throughput vs scalar FFMA)
// ---------------------------------------------------------------------------
__device__ __forceinline__ unsigned long long pk2(float a, float b) {
    unsigned long long r;
    asm("mov.b64 %0, {%1, %2};" : "=l"(r) : "f"(a), "f"(b));
    return r;
}
__device__ __forceinline__ void upk2(unsigned long long v, float& a, float& b) {
    asm("mov.b64 {%0, %1}, %2;" : "=f"(a), "=f"(b) : "l"(v));
}
__device__ __forceinline__ void ffma2(unsigned long long& d, unsigned long long a,
                                      unsigned long long b) {
    asm("fma.rn.f32x2 %0, %1, %2, %0;" : "+l"(d) : "l"(a), "l"(b));
}
__device__ __forceinline__ void fmul2(unsigned long long& d, unsigned long long a,
                                      unsigned long long b) {
    asm("mul.rn.f32x2 %0, %1, %2;" : "=l"(d) : "l"(a), "l"(b));
}

// ---------------------------------------------------------------------------
// Mask dtype detection: jax bool may arrive as 1-byte bool, int32 {0,1}, or
// float32 {0.0,1.0}. Rules on bytes [0, NB*NTOK):
//   no nonzero byte at (i%4)!=0            -> 4-byte (int32 0/1)
//   some byte outside {0,1}                -> 4-byte (float32 pattern bytes)
//   else                                   -> 1-byte bool
// In the 4-byte case "word != 0" is keep for both int32 and float32.
// ---------------------------------------------------------------------------
__global__ void detect_mask_kernel(const unsigned char* __restrict__ m, int nbytes) {
    __shared__ int sOdd, sWeird;
    if (threadIdx.x == 0) { sOdd = 0; sWeird = 0; }
    __syncthreads();
    int lodd = 0, lweird = 0;
    for (int i = threadIdx.x; i < nbytes; i += blockDim.x) {
        unsigned char v = m[i];
        if (v > 1) lweird = 1;
        if ((i & 3) && v) lodd = 1;
    }
    if (lodd) sOdd = 1;
    if (lweird) sWeird = 1;
    __syncthreads();
    if (threadIdx.x == 0) g_mask_is4 = ((sOdd == 0) || sWeird) ? 1 : 0;
}

// ---------------------------------------------------------------------------
// Flash-attention style kernel. One CTA = (batch, 64-query tile).
// Dynamic smem:
//   q_s  [DD][QP]  : x tile, transposed, pre-scaled by dot_scale
//   k_s  [DD][QP]  : m tile, transposed           (aliased with P_s [BN][QP])
//   v_s  [BN][DD]  : m tile, natural (also staging buffer for q load)
//   bias_s [BN], scale_s [DD]
// ---------------------------------------------------------------------------
__global__ void __launch_bounds__(NTHREADS, 1)
attn_kernel(const float* __restrict__ x, const float* __restrict__ mem,
            const unsigned char* __restrict__ mask8,
            const float* __restrict__ dscale, float* __restrict__ out)
{
    extern __shared__ float smem[];
    float* q_s     = smem;                 // DD*QP
    float* k_s     = smem + DD * QP;       // DD*QP (aliased with P_s)
    float* P_s     = k_s;                  // BN*QP  (<= DD*QP)
    float* v_s     = smem + 2 * DD * QP;   // BN*DD
    float* bias_s  = v_s + BN * DD;        // BN
    float* scale_s = bias_s + BN;          // DD

    const int b     = blockIdx.y;
    const int qbase = blockIdx.x * BM;
    const int tid   = threadIdx.x;
    const int tx    = tid & 15;            // column / dim-slice lane
    const int ty    = tid >> 4;            // row group
    const int r0    = ty * 4;
    const int c0    = tx * 4;
    const int dstart = tx * 16;
    const int warp  = tid >> 5;
    const int ln    = tid & 31;
    const bool is4  = (g_mask_is4 != 0);
    const int* mask32 = (const int*)mask8;

    for (int i = tid; i < DD; i += NTHREADS) scale_s[i] = dscale[i];

    // ---- load + transpose Q tile (scaled by dot_scale), staged via v_s ----
    {
        const float* xb = x + ((size_t)b * NTOK + qbase) * DD;
        for (int idx = tid; idx < BM * (DD / 4); idx += NTHREADS) {
            int d4 = idx & 63;
            int row = idx >> 6;
            float4 v = make_float4(0.f, 0.f, 0.f, 0.f);
            if (qbase + row < NTOK) v = *(const float4*)(xb + row * DD + d4 * 4);
            *(float4*)(v_s + row * DD + d4 * 4) = v;
        }
        __syncthreads();
        for (int r = warp; r < BM; r += 8) {
            #pragma unroll
            for (int d0 = 0; d0 < DD; d0 += 32) {
                int d = d0 + ln;
                q_s[d * QP + r] = v_s[r * DD + d] * scale_s[d];
            }
        }
    }

    // ---- flash accumulators ----
    unsigned long long O2[4][8];           // 4 rows x 16 dims (packed pairs)
    #pragma unroll
    for (int r = 0; r < 4; r++)
        #pragma unroll
        for (int j = 0; j < 8; j++) O2[r][j] = 0ull;
    float mrow[4] = { -1e30f, -1e30f, -1e30f, -1e30f };
    float lrow[4] = { 0.f, 0.f, 0.f, 0.f };   // per-lane partial sums (4 cols each)

    for (int kt = 0; kt < NKT; kt++) {
        const int kbase = kt * BN;
        __syncthreads();  // previous-iteration reads of v_s / P_s complete

        // ---- stage K/V tile (natural) + mask bias ----
        const float* mb = mem + ((size_t)b * NTOK + kbase) * DD;
        for (int idx = tid; idx < BN * (DD / 4); idx += NTHREADS) {
            int d4 = idx & 63;
            int row = idx >> 6;
            float4 v = make_float4(0.f, 0.f, 0.f, 0.f);
            if (kbase + row < NTOK) v = *(const float4*)(mb + row * DD + d4 * 4);
            *(float4*)(v_s + row * DD + d4 * 4) = v;
        }
        if (tid < BN) {
            int key = kbase + tid;
            float bias = -1e30f;
            if (key < NTOK) {
                int mi = b * NTOK + key;
                bool keep = is4 ? (mask32[mi] != 0) : (mask8[mi] != 0);
                if (keep) bias = 0.f;
            }
            bias_s[tid] = bias;
        }
        __syncthreads();

        // ---- transpose K into k_s[d][key] ----
        for (int r = warp; r < BN; r += 8) {
            #pragma unroll
            for (int d0 = 0; d0 < DD; d0 += 32) {
                int d = d0 + ln;
                k_s[d * QP + r] = v_s[r * DD + d];
            }
        }
        __syncthreads();

        // ---- S = Q_scaled @ K^T  (4x4 per thread, packed FFMA2) ----
        unsigned long long acc[4][2];
        #pragma unroll
        for (int r = 0; r < 4; r++) { acc[r][0] = 0ull; acc[r][1] = 0ull; }
        const float* qp = q_s + r0;
        const float* kp = k_s + c0;
        #pragma unroll 8
        for (int d = 0; d < DD; d++) {
            float4 qv = *(const float4*)(qp + d * QP);
            float4 kv = *(const float4*)(kp + d * QP);
            unsigned long long kA = pk2(kv.x, kv.y);
            unsigned long long kB = pk2(kv.z, kv.w);
            unsigned long long q0 = pk2(qv.x, qv.x);
            unsigned long long q1 = pk2(qv.y, qv.y);
            unsigned long long q2 = pk2(qv.z, qv.z);
            unsigned long long q3 = pk2(qv.w, qv.w);
            ffma2(acc[0][0], q0, kA); ffma2(acc[0][1], q0, kB);
            ffma2(acc[1][0], q1, kA); ffma2(acc[1][1], q1, kB);
            ffma2(acc[2][0], q2, kA); ffma2(acc[2][1], q2, kB);
            ffma2(acc[3][0], q3, kA); ffma2(acc[3][1], q3, kB);
        }

        // ---- bias + online softmax ----
        float s[4][4];
        #pragma unroll
        for (int r = 0; r < 4; r++) {
            upk2(acc[r][0], s[r][0], s[r][1]);
            upk2(acc[r][1], s[r][2], s[r][3]);
        }
        float bias0 = bias_s[c0 + 0], bias1 = bias_s[c0 + 1];
        float bias2 = bias_s[c0 + 2], bias3 = bias_s[c0 + 3];
        #pragma unroll
        for (int r = 0; r < 4; r++) {
            s[r][0] += bias0; s[r][1] += bias1; s[r][2] += bias2; s[r][3] += bias3;
        }
        #pragma unroll
        for (int r = 0; r < 4; r++) {
            float t = fmaxf(fmaxf(s[r][0], s[r][1]), fmaxf(s[r][2], s[r][3]));
            t = fmaxf(t, __shfl_xor_sync(0xffffffffu, t, 1));
            t = fmaxf(t, __shfl_xor_sync(0xffffffffu, t, 2));
            t = fmaxf(t, __shfl_xor_sync(0xffffffffu, t, 4));
            t = fmaxf(t, __shfl_xor_sync(0xffffffffu, t, 8));
            float mn  = fmaxf(mrow[r], t);
            float scl = __expf(mrow[r] - mn);
            mrow[r] = mn;
            float ls = 0.f;
            #pragma unroll
            for (int c = 0; c < 4; c++) {
                float p = __expf(s[r][c] - mn);
                s[r][c] = p;
                ls += p;
            }
            lrow[r] = lrow[r] * scl + ls;
            unsigned long long s2 = pk2(scl, scl);
            #pragma unroll
            for (int j = 0; j < 8; j++) fmul2(O2[r][j], O2[r][j], s2);
        }

        __syncthreads();  // everyone done reading k_s (P_s aliases it)

        // ---- write P transposed [key][row] ----
        #pragma unroll
        for (int c = 0; c < 4; c++) {
            float4 pv = make_float4(s[0][c], s[1][c], s[2][c], s[3][c]);
            *(float4*)(P_s + (c0 + c) * QP + r0) = pv;
        }
        __syncthreads();

        // ---- O += P @ V  (4 rows x 16 dims per thread) ----
        #pragma unroll 2
        for (int k = 0; k < BN; k++) {
            float4 pv = *(const float4*)(P_s + k * QP + r0);
            unsigned long long p0 = pk2(pv.x, pv.x);
            unsigned long long p1 = pk2(pv.y, pv.y);
            unsigned long long p2 = pk2(pv.z, pv.z);
            unsigned long long p3 = pk2(pv.w, pv.w);
            const ulonglong2* vp = (const ulonglong2*)(v_s + k * DD + dstart);
            ulonglong2 vA = vp[0];
            ulonglong2 vB = vp[1];
            ulonglong2 vC = vp[2];
            ulonglong2 vD = vp[3];
            ffma2(O2[0][0], p0, vA.x); ffma2(O2[0][1], p0, vA.y);
            ffma2(O2[0][2], p0, vB.x); ffma2(O2[0][3], p0, vB.y);
            ffma2(O2[0][4], p0, vC.x); ffma2(O2[0][5], p0, vC.y);
            ffma2(O2[0][6], p0, vD.x); ffma2(O2[0][7], p0, vD.y);
            ffma2(O2[1][0], p1, vA.x); ffma2(O2[1][1], p1, vA.y);
            ffma2(O2[1][2], p1, vB.x); ffma2(O2[1][3], p1, vB.y);
            ffma2(O2[1][4], p1, vC.x); ffma2(O2[1][5], p1, vC.y);
            ffma2(O2[1][6], p1, vD.x); ffma2(O2[1][7], p1, vD.y);
            ffma2(O2[2][0], p2, vA.x); ffma2(O2[2][1], p2, vA.y);
            ffma2(O2[2][2], p2, vB.x); ffma2(O2[2][3], p2, vB.y);
            ffma2(O2[2][4], p2, vC.x); ffma2(O2[2][5], p2, vC.y);
            ffma2(O2[2][6], p2, vD.x); ffma2(O2[2][7], p2, vD.y);
            ffma2(O2[3][0], p3, vA.x); ffma2(O2[3][1], p3, vA.y);
            ffma2(O2[3][2], p3, vB.x); ffma2(O2[3][3], p3, vB.y);
            ffma2(O2[3][4], p3, vC.x); ffma2(O2[3][5], p3, vC.y);
            ffma2(O2[3][6], p3, vD.x); ffma2(O2[3][7], p3, vD.y);
        }
    }

    // ---- finalize: total l across the 16 column lanes, normalize, store ----
    #pragma unroll
    for (int r = 0; r < 4; r++) {
        lrow[r] += __shfl_xor_sync(0xffffffffu, lrow[r], 1);
        lrow[r] += __shfl_xor_sync(0xffffffffu, lrow[r], 2);
        lrow[r] += __shfl_xor_sync(0xffffffffu, lrow[r], 4);
        lrow[r] += __shfl_xor_sync(0xffffffffu, lrow[r], 8);
    }
    #pragma unroll
    for (int r = 0; r < 4; r++) {
        int row = qbase + r0 + r;
        if (row >= NTOK) continue;
        float inv = 1.0f / lrow[r];
        float* op = out + ((size_t)b * NTOK + row) * (2 * DD) + DD + dstart;
        #pragma unroll
        for (int j = 0; j < 8; j += 2) {
            float a, bb, c, d;
            upk2(O2[r][j],     a, bb);
            upk2(O2[r][j + 1], c, d);
            float4 o4 = make_float4(a * inv, bb * inv, c * inv, d * inv);
            *(float4*)(op + (j / 2) * 4) = o4;
        }
    }

    // ---- copy x into out[..., :256] (straight from global; x is L2-hot) ----
    {
        const float* xb = x + ((size_t)b * NTOK + qbase) * DD;
        float* ob = out + ((size_t)b * NTOK + qbase) * (2 * DD);
        for (int idx = tid; idx < BM * (DD / 4); idx += NTHREADS) {
            int d4 = idx & 63;
            int row = idx >> 6;
            if (qbase + row < NTOK)
                *(float4*)(ob + row * (2 * DD) + d4 * 4) =
                    *(const float4*)(xb + row * DD + d4 * 4);
        }
    }
}

// ---------------------------------------------------------------------------
extern "C" void kernel_launch(void* const* d_in, const int* in_sizes, int n_in,
                              void* d_out, int out_size) {
    const float*         x      = (const float*)d_in[0];
    const float*         mem    = (const float*)d_in[1];
    const unsigned char* mask   = (const unsigned char*)d_in[2];
    // d_in[3] = w_lin : unused (constant along softmax axis -> cancels)
    const float*         dscale = (const float*)d_in[4];
    float*               out    = (float*)d_out;

    detect_mask_kernel<<<1, NTHREADS>>>(mask, NB * NTOK);

    const int smem_bytes = (2 * DD * QP + BN * DD + BN + DD) * (int)sizeof(float);
    cudaFuncSetAttribute(attn_kernel, cudaFuncAttributeMaxDynamicSharedMemorySize,
                         smem_bytes);
    dim3 grid(NQT, NB);
    attn_kernel<<<grid, NTHREADS, smem_bytes>>>(x, mem, mask, dscale, out);
}